// round 9
// baseline (speedup 1.0000x reference)
#include <cuda_runtime.h>
#include <cuda_bf16.h>
#include <mma.h>
#include <math.h>
#include <stdint.h>

using namespace nvcuda;

#define K_CODES 50257
#define D 144
#define NROWS 4096
#define MT 128
#define NT 128
#define NKSTEP 9                            // 144 / 16
#define CTILES ((K_CODES + NT - 1) / NT)    // 393
#define RTILES (NROWS / MT)                 // 32
#define CAP 1024
#define MARGIN 1e-4f
#define NZQ (NROWS * D)
#define NPART (NZQ / 256)
#define SLD 152                             // smem ldm for A/B tiles (bf16)
#define CLD 132                             // smem ldm for C tile (f32)
#define AB_BYTES (MT * SLD * 2)             // 38912 per tile

__device__ __nv_bfloat16 g_zb[NROWS * D];
__device__ __nv_bfloat16 g_eb[K_CODES * D];
__device__ float g_esq[K_CODES];
__device__ float g_rowsq[NROWS];
__device__ unsigned g_min[NROWS];
__device__ unsigned g_cnt[NROWS];
__device__ unsigned g_cand[NROWS * CAP];
__device__ unsigned g_bestidx[NROWS];
__device__ float g_partials[NPART];

// ---------------------------------------------------------------------------
__global__ void vq_init() {
    int i = blockIdx.x * blockDim.x + threadIdx.x;
    if (i < NROWS) { g_min[i] = 0x7F800000u; g_cnt[i] = 0u; }
}

// Fused: bf16 convert + squared-norm (warp per row). esq reduction kept as the
// same shfl tree that the passing kernels used (refine depends on g_esq bits).
__global__ void vq_prep_e(const float* __restrict__ emb) {
    int warp = (blockIdx.x * blockDim.x + threadIdx.x) >> 5;
    int lane = threadIdx.x & 31;
    if (warp >= K_CODES) return;
    const float* row = emb + (size_t)warp * D;
    __nv_bfloat16* rb = g_eb + (size_t)warp * D;
    float s = 0.f;
#pragma unroll
    for (int d = lane; d < D; d += 32) {
        float v = row[d];
        rb[d] = __float2bfloat16(v);
        s = fmaf(v, v, s);
    }
#pragma unroll
    for (int off = 16; off; off >>= 1) s += __shfl_xor_sync(~0u, s, off);
    if (lane == 0) g_esq[warp] = s;
}

// Fused: bf16 convert + rowsq (warp per row; rowsq only feeds the approx
// filter, so tree order is fine — exact refine recomputes rs itself).
__global__ void vq_prep_z(const float* __restrict__ z) {
    int warp = (blockIdx.x * blockDim.x + threadIdx.x) >> 5;
    int lane = threadIdx.x & 31;
    if (warp >= NROWS) return;
    const float* row = z + (size_t)warp * D;
    __nv_bfloat16* rb = g_zb + (size_t)warp * D;
    float s = 0.f;
#pragma unroll
    for (int d = lane; d < D; d += 32) {
        float v = row[d];
        rb[d] = __float2bfloat16(v);
        s = fmaf(v, v, s);
    }
#pragma unroll
    for (int off = 16; off; off >>= 1) s += __shfl_xor_sync(~0u, s, off);
    if (lane == 0) g_rowsq[warp] = s;
}

// ---------------------------------------------------------------------------
// Filter: 128x128 tile, 4 warps x (64x64) wmma -> approx d -> candidates
// ---------------------------------------------------------------------------
__global__ void __launch_bounds__(128) vq_mma() {
    extern __shared__ char sm[];
    __nv_bfloat16* As = (__nv_bfloat16*)sm;                // [128][SLD]
    __nv_bfloat16* Bs = (__nv_bfloat16*)(sm + AB_BYTES);   // [128][SLD]
    float*         Cs = (float*)sm;                         // [128][CLD] overlay

    const int tid = threadIdx.x;
    const int wid = tid >> 5;
    const int rowBase  = blockIdx.x * MT;
    const int codeBase = blockIdx.y * NT;
    const int wm = wid >> 1;     // 0..1 : 64-row band
    const int wn = wid & 1;      // 0..1 : 64-code band

    // Stage A (z rows) and B (codes) as 16B units (18 per row)
    for (int u = tid; u < MT * 18; u += 128) {
        int r = u / 18, c8 = (u % 18) * 8;
        *(uint4*)(As + r * SLD + c8) =
            *(const uint4*)(g_zb + (size_t)(rowBase + r) * D + c8);
    }
    for (int u = tid; u < NT * 18; u += 128) {
        int r = u / 18, c8 = (u % 18) * 8;
        uint4 v = make_uint4(0u, 0u, 0u, 0u);
        if (codeBase + r < K_CODES)
            v = *(const uint4*)(g_eb + (size_t)(codeBase + r) * D + c8);
        *(uint4*)(Bs + r * SLD + c8) = v;
    }
    __syncthreads();

    wmma::fragment<wmma::accumulator, 16, 16, 16, float> acc[4][4];
#pragma unroll
    for (int i = 0; i < 4; i++)
#pragma unroll
        for (int j = 0; j < 4; j++) wmma::fill_fragment(acc[i][j], 0.f);

#pragma unroll
    for (int ks = 0; ks < NKSTEP; ks++) {
        const int k = ks * 16;
        wmma::fragment<wmma::matrix_a, 16, 16, 16, __nv_bfloat16,
                       wmma::row_major> a[4];
        wmma::fragment<wmma::matrix_b, 16, 16, 16, __nv_bfloat16,
                       wmma::col_major> b[4];
#pragma unroll
        for (int i = 0; i < 4; i++)
            wmma::load_matrix_sync(a[i], As + (wm * 64 + i * 16) * SLD + k, SLD);
#pragma unroll
        for (int j = 0; j < 4; j++)
            wmma::load_matrix_sync(b[j], Bs + (wn * 64 + j * 16) * SLD + k, SLD);
#pragma unroll
        for (int i = 0; i < 4; i++)
#pragma unroll
            for (int j = 0; j < 4; j++)
                wmma::mma_sync(acc[i][j], a[i], b[j], acc[i][j]);
    }

    __syncthreads();   // A/B dead; Cs overlays them
#pragma unroll
    for (int i = 0; i < 4; i++)
#pragma unroll
        for (int j = 0; j < 4; j++)
            wmma::store_matrix_sync(
                Cs + (wm * 64 + i * 16) * CLD + (wn * 64 + j * 16),
                acc[i][j], CLD, wmma::mem_row_major);
    __syncthreads();

    // Epilogue: 1 thread per row, scan 128 codes
    const int rl  = tid;
    const int row = rowBase + rl;
    const float rs = g_rowsq[row];
    const float* crow = Cs + rl * CLD;

    float dmin = INFINITY;
#pragma unroll 8
    for (int c = 0; c < NT; c++) {
        if (codeBase + c < K_CODES) {
            float d = rs - 2.0f * crow[c];
            dmin = fminf(dmin, d);
        }
    }
    unsigned old = atomicMin(&g_min[row], __float_as_uint(dmin));
    float thr = fminf(__uint_as_float(old), dmin) + MARGIN;

#pragma unroll 8
    for (int c = 0; c < NT; c++) {
        int code = codeBase + c;
        if (code < K_CODES) {
            float d = rs - 2.0f * crow[c];
            if (d <= thr) {
                unsigned slot = atomicAdd(&g_cnt[row], 1u);
                if (slot < CAP) g_cand[(size_t)row * CAP + slot] = (unsigned)code;
            }
        }
    }
}

// ---------------------------------------------------------------------------
// Exact refine: bit-identical fp32 arithmetic of the proven-passing kernel
// ---------------------------------------------------------------------------
__global__ void __launch_bounds__(128) vq_refine(const float* __restrict__ z,
                                                 const float* __restrict__ emb) {
    __shared__ float zr[D];
    __shared__ float s_rs;
    __shared__ unsigned long long red[128];
    const int row = blockIdx.x;
    const int tid = threadIdx.x;

    for (int d = tid; d < D; d += 128) zr[d] = z[(size_t)row * D + d];
    __syncthreads();
    if (tid == 0) {
        float s = 0.f;
        for (int d = 0; d < D; d++) s = fmaf(zr[d], zr[d], s);
        s_rs = s;
    }
    __syncthreads();
    const float rs = s_rs;

    unsigned cnt = g_cnt[row];
    unsigned long long best = 0xFFFFFFFFFFFFFFFFull;

    if (cnt <= CAP) {
        for (unsigned i = tid; i < cnt; i += 128) {
            unsigned idx = g_cand[(size_t)row * CAP + i];
            const float* er = emb + (size_t)idx * D;
            float dot = 0.f;
            for (int d = 0; d < D; d++) dot = fmaf(zr[d], er[d], dot);
            float dv = (rs + g_esq[idx]) - 2.0f * dot;
            unsigned long long key =
                (((unsigned long long)__float_as_uint(dv)) << 32) | idx;
            if (key < best) best = key;
        }
    } else {  // overflow fallback: exact full scan (deterministic)
        for (unsigned idx = tid; idx < K_CODES; idx += 128) {
            const float* er = emb + (size_t)idx * D;
            float dot = 0.f;
            for (int d = 0; d < D; d++) dot = fmaf(zr[d], er[d], dot);
            float dv = (rs + g_esq[idx]) - 2.0f * dot;
            unsigned long long key =
                (((unsigned long long)__float_as_uint(dv)) << 32) | idx;
            if (key < best) best = key;
        }
    }
    red[tid] = best;
    __syncthreads();
#pragma unroll
    for (int s = 64; s; s >>= 1) {
        if (tid < s && red[tid + s] < red[tid]) red[tid] = red[tid + s];
        __syncthreads();
    }
    if (tid == 0) g_bestidx[row] = (unsigned)(red[0] & 0xFFFFFFFFull);
}

// ---------------------------------------------------------------------------
__global__ void vq_gather(const float* __restrict__ z,
                          const float* __restrict__ emb,
                          float* __restrict__ out, int out_size) {
    __shared__ float red[256];
    int i = blockIdx.x * 256 + threadIdx.x;
    float dsq = 0.f;
    if (i < NZQ) {
        int row = i / D;
        int col = i - row * D;
        unsigned idx = g_bestidx[row];
        float q = emb[(size_t)idx * D + col];
        out[i] = q;
        float df = q - z[i];
        dsq = df * df;
        if (col == 0 && out_size >= NZQ + NROWS)
            out[NZQ + row] = (float)idx;
    }
    red[threadIdx.x] = dsq;
    __syncthreads();
#pragma unroll
    for (int s = 128; s; s >>= 1) {
        if (threadIdx.x < s) red[threadIdx.x] += red[threadIdx.x + s];
        __syncthreads();
    }
    if (threadIdx.x == 0) g_partials[blockIdx.x] = red[0];
}

__global__ void vq_loss(float* __restrict__ out, int out_size) {
    __shared__ float red[256];
    float s = 0.f;
    for (int i = threadIdx.x; i < NPART; i += 256) s += g_partials[i];
    red[threadIdx.x] = s;
    __syncthreads();
#pragma unroll
    for (int k = 128; k; k >>= 1) {
        if (threadIdx.x < k) red[threadIdx.x] += red[threadIdx.x + k];
        __syncthreads();
    }
    if (threadIdx.x == 0 && out_size >= NZQ + NROWS + 1)
        out[NZQ + NROWS] = red[0] / (float)NZQ;
}

// ---------------------------------------------------------------------------
extern "C" void kernel_launch(void* const* d_in, const int* in_sizes, int n_in,
                              void* d_out, int out_size) {
    const float* z   = (const float*)d_in[0];
    const float* emb = (const float*)d_in[1];
    float* out = (float*)d_out;

    const int smemBytes = 2 * AB_BYTES;   // 77824 (C overlays A+B)
    cudaFuncSetAttribute(vq_mma, cudaFuncAttributeMaxDynamicSharedMemorySize,
                         smemBytes);

    cudaMemsetAsync(d_out, 0, (size_t)out_size * sizeof(float));

    vq_init<<<(NROWS + 255) / 256, 256>>>();
    vq_prep_z<<<(NROWS * 32 + 255) / 256, 256>>>(z);
    vq_prep_e<<<(K_CODES * 32 + 255) / 256, 256>>>(emb);

    dim3 grid(RTILES, CTILES);   // 32 x 393
    vq_mma<<<grid, 128, smemBytes>>>();

    vq_refine<<<NROWS, 128>>>(z, emb);
    vq_gather<<<NPART, 256>>>(z, emb, out, out_size);
    vq_loss<<<1, 256>>>(out, out_size);
}

// round 10
// speedup vs baseline: 1.0015x; 1.0015x over previous
#include <cuda_runtime.h>
#include <cuda_bf16.h>
#include <mma.h>
#include <math.h>
#include <stdint.h>

using namespace nvcuda;

#define K_CODES 50257
#define D 144
#define NROWS 4096
#define MT 128
#define NT 128
#define NKSTEP 9                            // 144 / 16
#define CTILES ((K_CODES + NT - 1) / NT)    // 393
#define RTILES (NROWS / MT)                 // 32
#define CAP 1024
#define MARGIN 1e-4f
#define NZQ (NROWS * D)
#define NPART (NZQ / 256)
#define SLD 152                             // smem ldm for A/B tiles (bf16)
#define CLD 132                             // smem ldm for C tile (f32)
#define AB_BYTES (MT * SLD * 2)             // 38912 per tile

__device__ __nv_bfloat16 g_zb[NROWS * D];
__device__ __nv_bfloat16 g_eb[K_CODES * D];
__device__ float g_esq[K_CODES];
__device__ float g_rowsq[NROWS];
__device__ unsigned g_min[NROWS];
__device__ unsigned g_cnt[NROWS];
__device__ unsigned g_cand[NROWS * CAP];
__device__ unsigned g_bestidx[NROWS];
__device__ float g_partials[NPART];

// ---------------------------------------------------------------------------
__global__ void vq_init() {
    int i = blockIdx.x * blockDim.x + threadIdx.x;
    if (i < NROWS) { g_min[i] = 0x7F800000u; g_cnt[i] = 0u; }
}

// Fused: bf16 convert + squared-norm (warp per row). esq reduction kept as the
// same shfl tree that the passing kernels used (refine depends on g_esq bits).
__global__ void vq_prep_e(const float* __restrict__ emb) {
    int warp = (blockIdx.x * blockDim.x + threadIdx.x) >> 5;
    int lane = threadIdx.x & 31;
    if (warp >= K_CODES) return;
    const float* row = emb + (size_t)warp * D;
    __nv_bfloat16* rb = g_eb + (size_t)warp * D;
    float s = 0.f;
#pragma unroll
    for (int d = lane; d < D; d += 32) {
        float v = row[d];
        rb[d] = __float2bfloat16(v);
        s = fmaf(v, v, s);
    }
#pragma unroll
    for (int off = 16; off; off >>= 1) s += __shfl_xor_sync(~0u, s, off);
    if (lane == 0) g_esq[warp] = s;
}

// Fused: bf16 convert + rowsq (warp per row; rowsq only feeds the approx
// filter, so tree order is fine — exact refine recomputes rs itself).
__global__ void vq_prep_z(const float* __restrict__ z) {
    int warp = (blockIdx.x * blockDim.x + threadIdx.x) >> 5;
    int lane = threadIdx.x & 31;
    if (warp >= NROWS) return;
    const float* row = z + (size_t)warp * D;
    __nv_bfloat16* rb = g_zb + (size_t)warp * D;
    float s = 0.f;
#pragma unroll
    for (int d = lane; d < D; d += 32) {
        float v = row[d];
        rb[d] = __float2bfloat16(v);
        s = fmaf(v, v, s);
    }
#pragma unroll
    for (int off = 16; off; off >>= 1) s += __shfl_xor_sync(~0u, s, off);
    if (lane == 0) g_rowsq[warp] = s;
}

// ---------------------------------------------------------------------------
// Filter: 128x128 tile, 4 warps x (64x64) wmma -> approx d -> candidates
// ---------------------------------------------------------------------------
__global__ void __launch_bounds__(128) vq_mma() {
    extern __shared__ char sm[];
    __nv_bfloat16* As = (__nv_bfloat16*)sm;                // [128][SLD]
    __nv_bfloat16* Bs = (__nv_bfloat16*)(sm + AB_BYTES);   // [128][SLD]
    float*         Cs = (float*)sm;                         // [128][CLD] overlay

    const int tid = threadIdx.x;
    const int wid = tid >> 5;
    const int rowBase  = blockIdx.x * MT;
    const int codeBase = blockIdx.y * NT;
    const int wm = wid >> 1;     // 0..1 : 64-row band
    const int wn = wid & 1;      // 0..1 : 64-code band

    // Stage A (z rows) and B (codes) as 16B units (18 per row)
    for (int u = tid; u < MT * 18; u += 128) {
        int r = u / 18, c8 = (u % 18) * 8;
        *(uint4*)(As + r * SLD + c8) =
            *(const uint4*)(g_zb + (size_t)(rowBase + r) * D + c8);
    }
    for (int u = tid; u < NT * 18; u += 128) {
        int r = u / 18, c8 = (u % 18) * 8;
        uint4 v = make_uint4(0u, 0u, 0u, 0u);
        if (codeBase + r < K_CODES)
            v = *(const uint4*)(g_eb + (size_t)(codeBase + r) * D + c8);
        *(uint4*)(Bs + r * SLD + c8) = v;
    }
    __syncthreads();

    wmma::fragment<wmma::accumulator, 16, 16, 16, float> acc[4][4];
#pragma unroll
    for (int i = 0; i < 4; i++)
#pragma unroll
        for (int j = 0; j < 4; j++) wmma::fill_fragment(acc[i][j], 0.f);

#pragma unroll
    for (int ks = 0; ks < NKSTEP; ks++) {
        const int k = ks * 16;
        wmma::fragment<wmma::matrix_a, 16, 16, 16, __nv_bfloat16,
                       wmma::row_major> a[4];
        wmma::fragment<wmma::matrix_b, 16, 16, 16, __nv_bfloat16,
                       wmma::col_major> b[4];
#pragma unroll
        for (int i = 0; i < 4; i++)
            wmma::load_matrix_sync(a[i], As + (wm * 64 + i * 16) * SLD + k, SLD);
#pragma unroll
        for (int j = 0; j < 4; j++)
            wmma::load_matrix_sync(b[j], Bs + (wn * 64 + j * 16) * SLD + k, SLD);
#pragma unroll
        for (int i = 0; i < 4; i++)
#pragma unroll
            for (int j = 0; j < 4; j++)
                wmma::mma_sync(acc[i][j], a[i], b[j], acc[i][j]);
    }

    __syncthreads();   // A/B dead; Cs overlays them
#pragma unroll
    for (int i = 0; i < 4; i++)
#pragma unroll
        for (int j = 0; j < 4; j++)
            wmma::store_matrix_sync(
                Cs + (wm * 64 + i * 16) * CLD + (wn * 64 + j * 16),
                acc[i][j], CLD, wmma::mem_row_major);
    __syncthreads();

    // Epilogue: 1 thread per row, scan 128 codes
    const int rl  = tid;
    const int row = rowBase + rl;
    const float rs = g_rowsq[row];
    const float* crow = Cs + rl * CLD;

    float dmin = INFINITY;
#pragma unroll 8
    for (int c = 0; c < NT; c++) {
        if (codeBase + c < K_CODES) {
            float d = rs - 2.0f * crow[c];
            dmin = fminf(dmin, d);
        }
    }
    unsigned old = atomicMin(&g_min[row], __float_as_uint(dmin));
    float thr = fminf(__uint_as_float(old), dmin) + MARGIN;

#pragma unroll 8
    for (int c = 0; c < NT; c++) {
        int code = codeBase + c;
        if (code < K_CODES) {
            float d = rs - 2.0f * crow[c];
            if (d <= thr) {
                unsigned slot = atomicAdd(&g_cnt[row], 1u);
                if (slot < CAP) g_cand[(size_t)row * CAP + slot] = (unsigned)code;
            }
        }
    }
}

// ---------------------------------------------------------------------------
// Exact refine: bit-identical fp32 arithmetic of the proven-passing kernel
// ---------------------------------------------------------------------------
__global__ void __launch_bounds__(128) vq_refine(const float* __restrict__ z,
                                                 const float* __restrict__ emb) {
    __shared__ float zr[D];
    __shared__ float s_rs;
    __shared__ unsigned long long red[128];
    const int row = blockIdx.x;
    const int tid = threadIdx.x;

    for (int d = tid; d < D; d += 128) zr[d] = z[(size_t)row * D + d];
    __syncthreads();
    if (tid == 0) {
        float s = 0.f;
        for (int d = 0; d < D; d++) s = fmaf(zr[d], zr[d], s);
        s_rs = s;
    }
    __syncthreads();
    const float rs = s_rs;

    unsigned cnt = g_cnt[row];
    unsigned long long best = 0xFFFFFFFFFFFFFFFFull;

    if (cnt <= CAP) {
        for (unsigned i = tid; i < cnt; i += 128) {
            unsigned idx = g_cand[(size_t)row * CAP + i];
            const float* er = emb + (size_t)idx * D;
            float dot = 0.f;
            for (int d = 0; d < D; d++) dot = fmaf(zr[d], er[d], dot);
            float dv = (rs + g_esq[idx]) - 2.0f * dot;
            unsigned long long key =
                (((unsigned long long)__float_as_uint(dv)) << 32) | idx;
            if (key < best) best = key;
        }
    } else {  // overflow fallback: exact full scan (deterministic)
        for (unsigned idx = tid; idx < K_CODES; idx += 128) {
            const float* er = emb + (size_t)idx * D;
            float dot = 0.f;
            for (int d = 0; d < D; d++) dot = fmaf(zr[d], er[d], dot);
            float dv = (rs + g_esq[idx]) - 2.0f * dot;
            unsigned long long key =
                (((unsigned long long)__float_as_uint(dv)) << 32) | idx;
            if (key < best) best = key;
        }
    }
    red[tid] = best;
    __syncthreads();
#pragma unroll
    for (int s = 64; s; s >>= 1) {
        if (tid < s && red[tid + s] < red[tid]) red[tid] = red[tid + s];
        __syncthreads();
    }
    if (tid == 0) g_bestidx[row] = (unsigned)(red[0] & 0xFFFFFFFFull);
}

// ---------------------------------------------------------------------------
__global__ void vq_gather(const float* __restrict__ z,
                          const float* __restrict__ emb,
                          float* __restrict__ out, int out_size) {
    __shared__ float red[256];
    int i = blockIdx.x * 256 + threadIdx.x;
    float dsq = 0.f;
    if (i < NZQ) {
        int row = i / D;
        int col = i - row * D;
        unsigned idx = g_bestidx[row];
        float q = emb[(size_t)idx * D + col];
        out[i] = q;
        float df = q - z[i];
        dsq = df * df;
        if (col == 0 && out_size >= NZQ + NROWS)
            out[NZQ + row] = (float)idx;
    }
    red[threadIdx.x] = dsq;
    __syncthreads();
#pragma unroll
    for (int s = 128; s; s >>= 1) {
        if (threadIdx.x < s) red[threadIdx.x] += red[threadIdx.x + s];
        __syncthreads();
    }
    if (threadIdx.x == 0) g_partials[blockIdx.x] = red[0];
}

__global__ void vq_loss(float* __restrict__ out, int out_size) {
    __shared__ float red[256];
    float s = 0.f;
    for (int i = threadIdx.x; i < NPART; i += 256) s += g_partials[i];
    red[threadIdx.x] = s;
    __syncthreads();
#pragma unroll
    for (int k = 128; k; k >>= 1) {
        if (threadIdx.x < k) red[threadIdx.x] += red[threadIdx.x + k];
        __syncthreads();
    }
    if (threadIdx.x == 0 && out_size >= NZQ + NROWS + 1)
        out[NZQ + NROWS] = red[0] / (float)NZQ;
}

// ---------------------------------------------------------------------------
extern "C" void kernel_launch(void* const* d_in, const int* in_sizes, int n_in,
                              void* d_out, int out_size) {
    const float* z   = (const float*)d_in[0];
    const float* emb = (const float*)d_in[1];
    float* out = (float*)d_out;

    const int smemBytes = 2 * AB_BYTES;   // 77824 (C overlays A+B)
    cudaFuncSetAttribute(vq_mma, cudaFuncAttributeMaxDynamicSharedMemorySize,
                         smemBytes);

    cudaMemsetAsync(d_out, 0, (size_t)out_size * sizeof(float));

    vq_init<<<(NROWS + 255) / 256, 256>>>();
    vq_prep_z<<<(NROWS * 32 + 255) / 256, 256>>>(z);
    vq_prep_e<<<(K_CODES * 32 + 255) / 256, 256>>>(emb);

    dim3 grid(RTILES, CTILES);   // 32 x 393
    vq_mma<<<grid, 128, smemBytes>>>();

    vq_refine<<<NROWS, 128>>>(z, emb);
    vq_gather<<<NPART, 256>>>(z, emb, out, out_size);
    vq_loss<<<1, 256>>>(out, out_size);
}